// round 13
// baseline (speedup 1.0000x reference)
#include <cuda_runtime.h>
#include <cuda_fp16.h>
#include <stdint.h>
#include <math.h>

#define NBATCH 8192
#define NS 16
#define DIM 256
#define PF 48
#define NROWS (NBATCH*NS)   /* 131072 */
#define EPSC 1e-5f
#define ATT_SCALE 0.17677669529663687f
#define PSH 56    /* prs stride (halves): 7 chunks, step 7 mod 8 -> conflict-free */
#define HSH 264   /* 256-col fp16 A tile stride (halves): 33 chunks, step 1 */
#define B1SH 56   /* layer1 B stride */
#define B2SH 72   /* 64-k chunk stride (attnproj proj) */
#define BC 40     /* 32-k chunk stride (mlpqkv): 5 chunks, step 5 mod 8 -> ok */
#define ASH 40    /* attention per-head 16x32 tile stride */

/* ---------------- device scratch ---------------- */
__device__ float g_part_S[256][PF*PF];
__device__ float g_part_m[256][PF];
__device__ float g_S[PF*PF];
__device__ float g_m[PF];
__device__ __half g_w1h[3][256*PF];
__device__ float  g_b1e[3][DIM];
__device__ __half g_qkvwh[768*256];
__device__ __half g_w2h[3][256*256];
__device__ __half g_projh[256*256];
__device__ __half g_posh[3][(long)NROWS*256];
__device__ __half g_qkvh[(long)NROWS*768];

/* ---------------- helpers ---------------- */
__device__ __forceinline__ void mma_f16(float& c0, float& c1, float& c2, float& c3,
                                        uint32_t a0, uint32_t a1, uint32_t a2, uint32_t a3,
                                        uint32_t b0, uint32_t b1) {
    asm volatile("mma.sync.aligned.m16n8k16.row.col.f32.f16.f16.f32 "
                 "{%0,%1,%2,%3},{%4,%5,%6,%7},{%8,%9},{%0,%1,%2,%3};"
                 : "+f"(c0), "+f"(c1), "+f"(c2), "+f"(c3)
                 : "r"(a0), "r"(a1), "r"(a2), "r"(a3), "r"(b0), "r"(b1));
}
__device__ __forceinline__ uint32_t sptr(const void* p) {
    return (uint32_t)__cvta_generic_to_shared(p);
}
__device__ __forceinline__ void ldsm4(uint32_t& r0, uint32_t& r1, uint32_t& r2, uint32_t& r3,
                                      uint32_t addr) {
    asm volatile("ldmatrix.sync.aligned.m8n8.x4.shared.b16 {%0,%1,%2,%3}, [%4];"
                 : "=r"(r0), "=r"(r1), "=r"(r2), "=r"(r3) : "r"(addr));
}
__device__ __forceinline__ void ldsm4t(uint32_t& r0, uint32_t& r1, uint32_t& r2, uint32_t& r3,
                                       uint32_t addr) {
    asm volatile("ldmatrix.sync.aligned.m8n8.x4.trans.shared.b16 {%0,%1,%2,%3}, [%4];"
                 : "=r"(r0), "=r"(r1), "=r"(r2), "=r"(r3) : "r"(addr));
}
__device__ __forceinline__ uint32_t h2_as_u32(__half2 h) {
    uint32_t u;
    __builtin_memcpy(&u, &h, 4);
    return u;
}
__device__ __forceinline__ __half2 u32_as_h2(uint32_t u) {
    __half2 h;
    __builtin_memcpy(&h, &u, 4);
    return h;
}
__device__ __forceinline__ uint32_t pack_h2(float a, float b) {
    return h2_as_u32(__floats2half2_rn(a, b));
}
__device__ __forceinline__ int4 hadd2x4(int4 a, int4 b) {
    int4 r;
    r.x = (int)h2_as_u32(__hadd2(u32_as_h2((uint32_t)a.x), u32_as_h2((uint32_t)b.x)));
    r.y = (int)h2_as_u32(__hadd2(u32_as_h2((uint32_t)a.y), u32_as_h2((uint32_t)b.y)));
    r.z = (int)h2_as_u32(__hadd2(u32_as_h2((uint32_t)a.z), u32_as_h2((uint32_t)b.z)));
    r.w = (int)h2_as_u32(__hadd2(u32_as_h2((uint32_t)a.w), u32_as_h2((uint32_t)b.w)));
    return r;
}
__device__ __forceinline__ void cpa16(uint32_t dst, const void* src) {
    asm volatile("cp.async.cg.shared.global [%0], [%1], 16;" :: "r"(dst), "l"(src));
}
#define CPA_COMMIT() asm volatile("cp.async.commit_group;" ::: "memory")
#define CPA_WAIT0()  asm volatile("cp.async.wait_group 0;" ::: "memory")

/* ---------------- 1) partial stats ---------------- */
__global__ void k_stats_part(const float* __restrict__ pr) {
    __shared__ float ps[64*PF];
    int tid = threadIdx.x;
    int ti = tid >> 4, tj = tid & 15;
    float acc[9]; float asum[3];
#pragma unroll
    for (int i = 0; i < 9; i++) acc[i] = 0.f;
    asum[0] = asum[1] = asum[2] = 0.f;
    int r0 = blockIdx.x * 512;
    for (int t = 0; t < 8; t++) {
        const float* src = pr + (long)(r0 + t*64) * PF;
        for (int i = tid; i < 64*PF; i += 256) ps[i] = src[i];
        __syncthreads();
        for (int r = 0; r < 64; r++) {
            float si0 = ps[r*PF + 3*ti + 0];
            float si1 = ps[r*PF + 3*ti + 1];
            float si2 = ps[r*PF + 3*ti + 2];
            float sj0 = ps[r*PF + 3*tj + 0];
            float sj1 = ps[r*PF + 3*tj + 1];
            float sj2 = ps[r*PF + 3*tj + 2];
            acc[0] += si0*sj0; acc[1] += si0*sj1; acc[2] += si0*sj2;
            acc[3] += si1*sj0; acc[4] += si1*sj1; acc[5] += si1*sj2;
            acc[6] += si2*sj0; acc[7] += si2*sj1; acc[8] += si2*sj2;
            if (tj == 0) { asum[0] += si0; asum[1] += si1; asum[2] += si2; }
        }
        __syncthreads();
    }
#pragma unroll
    for (int a = 0; a < 3; a++)
#pragma unroll
        for (int bq = 0; bq < 3; bq++)
            g_part_S[blockIdx.x][(3*ti + a)*PF + 3*tj + bq] = acc[a*3 + bq];
    if (tj == 0) {
        g_part_m[blockIdx.x][3*ti + 0] = asum[0];
        g_part_m[blockIdx.x][3*ti + 1] = asum[1];
        g_part_m[blockIdx.x][3*ti + 2] = asum[2];
    }
}

/* ---------------- 2) final reduce ---------------- */
__global__ void k_stats_red() {
    int i = blockIdx.x * 256 + threadIdx.x;
    if (i < PF*PF) {
        float s = 0.f;
        for (int c = 0; c < 256; c++) s += g_part_S[c][i];
        g_S[i] = s;
    } else if (i < PF*PF + PF) {
        int j = i - PF*PF;
        float s = 0.f;
        for (int c = 0; c < 256; c++) s += g_part_m[c][j];
        g_m[j] = s * (1.f / (float)NROWS);
    }
}

/* ---------------- 3) fp32 -> fp16 weight convert ---------------- */
__global__ void k_prep(const float* __restrict__ qkvw, const float* __restrict__ w2q,
                       const float* __restrict__ w2k, const float* __restrict__ w2v,
                       const float* __restrict__ projw) {
    int i4 = blockIdx.x * blockDim.x + threadIdx.x;
    const int N0 = 768*256/4;
    const int N1 = N0 + 3*65536/4;
    const int NT = N1 + 65536/4;
    if (i4 >= NT) return;
    const float* src; __half* dst; int j;
    if (i4 < N0) { src = qkvw; dst = g_qkvwh; j = i4; }
    else if (i4 < N1) {
        j = i4 - N0;
        int p = j / 16384; j -= p * 16384;
        src = (p == 0 ? w2q : (p == 1 ? w2k : w2v));
        dst = g_w2h[p];
    } else { src = projw; dst = g_projh; j = i4 - N1; }
    float4 v = *(const float4*)(src + j*4);
    __half2* d = (__half2*)(dst + j*4);
    d[0] = __floats2half2_rn(v.x, v.y);
    d[1] = __floats2half2_rn(v.z, v.w);
}

/* ---------------- 4) fold BN into layer-1 affine ---------------- */
__global__ void k_fold(const float* __restrict__ qw1, const float* __restrict__ qb1,
                       const float* __restrict__ qg,  const float* __restrict__ qbe,
                       const float* __restrict__ kw1, const float* __restrict__ kb1,
                       const float* __restrict__ kg,  const float* __restrict__ kbe,
                       const float* __restrict__ vw1, const float* __restrict__ vb1,
                       const float* __restrict__ vg,  const float* __restrict__ vbe) {
    __shared__ float ws[8][PF];
    int tid = threadIdx.x;
    int wl = tid >> 5, lane = tid & 31;
    int ch = blockIdx.x * 8 + wl;
    int p = ch >> 8, c = ch & 255;
    const float* w1 = (p == 0 ? qw1 : (p == 1 ? kw1 : vw1)) + c*PF;
    const float* b1 = (p == 0 ? qb1 : (p == 1 ? kb1 : vb1));
    const float* gg = (p == 0 ? qg  : (p == 1 ? kg  : vg ));
    const float* be = (p == 0 ? qbe : (p == 1 ? kbe : vbe));
    ws[wl][lane] = w1[lane];
    if (lane < PF - 32) ws[wl][lane + 32] = w1[lane + 32];
    __syncwarp();
    float quad = 0.f, wm = 0.f;
#pragma unroll
    for (int ii = 0; ii < 2; ii++) {
        int i = lane + ii*32;
        if (i < PF) {
            float wi = ws[wl][i];
            float t = 0.f;
            for (int j = 0; j < PF; j++) t += g_S[i*PF + j] * ws[wl][j];
            quad += wi * t;
            wm   += wi * g_m[i];
        }
    }
    for (int off = 16; off > 0; off >>= 1) {
        quad += __shfl_xor_sync(0xffffffffu, quad, off);
        wm   += __shfl_xor_sync(0xffffffffu, wm,   off);
    }
    float var   = quad * (1.f / (float)NROWS) - wm * wm;
    float scale = gg[c] * rsqrtf(var + EPSC);
    float mu    = wm + b1[c];
    float b1e   = (b1[c] - mu) * scale + be[c];
#pragma unroll
    for (int ii = 0; ii < 2; ii++) {
        int j = lane + ii*32;
        if (j < PF) g_w1h[p][c*PF + j] = __float2half(ws[wl][j] * scale);
    }
    if (lane == 0) g_b1e[p][c] = b1e;
}

/* ---------------- 5) merged pos-MLPs + qkv (grid 2048, 128 rows/CTA, 2 CTAs/SM) ---- */
#define BSM_OFF (128*PSH + 128*HSH)
__global__ void __launch_bounds__(256, 2) k_mlpqkv(const float* __restrict__ pr,
        const float* __restrict__ qb2, const float* __restrict__ kb2,
        const float* __restrict__ vb2, const float* __restrict__ x) {
    extern __shared__ __half smh[];
    __half* bsm = smh + BSM_OFF;              /* 2 x 128 x BC */
    int tid = threadIdx.x;
    int wid = tid >> 5, lane = tid & 31;
    int g = lane >> 2, t = lane & 3;
    int a_row = wid*16 + (lane & 15);
    int a_koff = (lane & 16) ? 8 : 0;
    int b_nrow = (lane & 7) + ((lane & 16) ? 8 : 0);
    int b_koff = (lane & 8) ? 8 : 0;

    if (blockIdx.x < 1024) {
        /* ================= posmlp branch (128 rows) ================= */
        __half* prs = smh;
        __half* hs  = smh + 128*PSH;
        int r0 = blockIdx.x * 128;

        for (int i = tid; i < 128*12; i += 256) {
            int row = i / 12, c4 = i % 12;
            float4 v = *(const float4*)(pr + (long)(r0 + row)*PF + c4*4);
            __half2* d = (__half2*)(prs + row*PSH + c4*4);
            d[0] = __floats2half2_rn(v.x, v.y);
            d[1] = __floats2half2_rn(v.z, v.w);
        }
        __syncthreads();

        for (int p = 0; p < 3; p++) {
            const float* b1 = g_b1e[p];
            /* ---- L1: two n-halves, B staged per half ---- */
            for (int nc = 0; nc < 2; nc++) {
                for (int i = tid; i < 128*6; i += 256) {
                    int row = i / 6, c8 = i % 6;
                    cpa16(sptr(bsm + row*B1SH + c8*8),
                          g_w1h[p] + (nc*128 + row)*PF + c8*8);
                }
                CPA_COMMIT(); CPA_WAIT0();
                __syncthreads();
                float acc[16][4];
#pragma unroll
                for (int nb = 0; nb < 16; nb++) {
                    acc[nb][0]=0.f; acc[nb][1]=0.f; acc[nb][2]=0.f; acc[nb][3]=0.f;
                }
#pragma unroll
                for (int ks = 0; ks < 3; ks++) {
                    uint32_t A0[4];
                    ldsm4(A0[0],A0[1],A0[2],A0[3], sptr(prs + a_row*PSH + ks*16 + a_koff));
#pragma unroll
                    for (int np = 0; np < 8; np++) {
                        int cb = np*16 + b_nrow;
                        uint32_t b0,b1r,b2,b3;
                        ldsm4(b0,b1r,b2,b3, sptr(bsm + cb*B1SH + ks*16 + b_koff));
                        mma_f16(acc[2*np][0],acc[2*np][1],acc[2*np][2],acc[2*np][3],
                                A0[0],A0[1],A0[2],A0[3], b0,b1r);
                        mma_f16(acc[2*np+1][0],acc[2*np+1][1],acc[2*np+1][2],acc[2*np+1][3],
                                A0[0],A0[1],A0[2],A0[3], b2,b3);
                    }
                }
#pragma unroll
                for (int nb = 0; nb < 16; nb++) {
                    int col = nc*128 + nb*8 + 2*t;
                    int rowa = wid*16 + g;
                    float bb0 = __ldg(&b1[col]), bb1 = __ldg(&b1[col+1]);
                    *(__half2*)(hs + rowa*HSH + col) =
                        __floats2half2_rn(fmaxf(acc[nb][0]+bb0, 0.f), fmaxf(acc[nb][1]+bb1, 0.f));
                    *(__half2*)(hs + (rowa+8)*HSH + col) =
                        __floats2half2_rn(fmaxf(acc[nb][2]+bb0, 0.f), fmaxf(acc[nb][3]+bb1, 0.f));
                }
                __syncthreads();
            }
            /* ---- L2: 16 continuous 32-k chunks (nc = c>>3, kc = c&7) ---- */
            const float* b2 = (p == 0 ? qb2 : (p == 1 ? kb2 : vb2));
            for (int i = tid; i < 128*4; i += 256) {
                int row = i >> 2, c8 = i & 3;
                cpa16(sptr(bsm + row*BC + c8*8), g_w2h[p] + row*256 + c8*8);
            }
            CPA_COMMIT();
            float acc[16][4];
            for (int c = 0; c < 16; c++) {
                int nc = c >> 3, kc = c & 7;
                __half* bcur = bsm + (c & 1)*128*BC;
                CPA_WAIT0();
                __syncthreads();
                if (c < 15) {
                    int cn = c + 1;
                    __half* bnxt = bsm + (cn & 1)*128*BC;
                    const __half* src = g_w2h[p] + (long)((cn >> 3)*128)*256 + (cn & 7)*32;
                    for (int i = tid; i < 128*4; i += 256) {
                        int row = i >> 2, c8 = i & 3;
                        cpa16(sptr(bnxt + row*BC + c8*8), src + row*256 + c8*8);
                    }
                    CPA_COMMIT();
                }
                if (kc == 0) {
#pragma unroll
                    for (int nb = 0; nb < 16; nb++) {
                        acc[nb][0]=0.f; acc[nb][1]=0.f; acc[nb][2]=0.f; acc[nb][3]=0.f;
                    }
                }
#pragma unroll
                for (int kk = 0; kk < 2; kk++) {
                    uint32_t A0[4];
                    ldsm4(A0[0],A0[1],A0[2],A0[3],
                          sptr(hs + a_row*HSH + kc*32 + kk*16 + a_koff));
#pragma unroll
                    for (int np = 0; np < 8; np++) {
                        int cb = np*16 + b_nrow;
                        uint32_t b0,b1r,b2,b3;
                        ldsm4(b0,b1r,b2,b3, sptr(bcur + cb*BC + kk*16 + b_koff));
                        mma_f16(acc[2*np][0],acc[2*np][1],acc[2*np][2],acc[2*np][3],
                                A0[0],A0[1],A0[2],A0[3], b0,b1r);
                        mma_f16(acc[2*np+1][0],acc[2*np+1][1],acc[2*np+1][2],acc[2*np+1][3],
                                A0[0],A0[1],A0[2],A0[3], b2,b3);
                    }
                }
                if (kc == 7) {
#pragma unroll
                    for (int nb = 0; nb < 16; nb++) {
                        int col = nc*128 + nb*8 + 2*t;
                        int rowa = wid*16 + g;
                        float bb0 = __ldg(&b2[col]), bb1 = __ldg(&b2[col+1]);
                        long gr = r0 + rowa;
                        *(__half2*)(&g_posh[p][gr*256 + col]) =
                            __floats2half2_rn(acc[nb][0]+bb0, acc[nb][1]+bb1);
                        *(__half2*)(&g_posh[p][(gr+8)*256 + col]) =
                            __floats2half2_rn(acc[nb][2]+bb0, acc[nb][3]+bb1);
                    }
                }
            }
            __syncthreads();
        }
    } else {
        /* ================= qkv branch: 48 continuous 32-k chunks ================= */
        __half* xs = smh;
        int r0 = (blockIdx.x - 1024) * 128;

        for (int i = tid; i < 128*64; i += 256) {
            int row = i >> 6, c4 = i & 63;
            float4 v = *(const float4*)(x + (long)(r0 + row)*DIM + c4*4);
            __half2* d = (__half2*)(xs + row*HSH + c4*4);
            d[0] = __floats2half2_rn(v.x, v.y);
            d[1] = __floats2half2_rn(v.z, v.w);
        }
        for (int i = tid; i < 128*4; i += 256) {
            int row = i >> 2, c8 = i & 3;
            cpa16(sptr(bsm + row*BC + c8*8), g_qkvwh + row*256 + c8*8);
        }
        CPA_COMMIT();
        __syncthreads();

        float acc[16][4];
        for (int c = 0; c < 48; c++) {
            int nc = c >> 3, kc = c & 7;
            __half* bcur = bsm + (c & 1)*128*BC;
            CPA_WAIT0();
            __syncthreads();
            if (c < 47) {
                int cn = c + 1;
                __half* bnxt = bsm + (cn & 1)*128*BC;
                const __half* src = g_qkvwh + (long)((cn >> 3)*128)*256 + (cn & 7)*32;
                for (int i = tid; i < 128*4; i += 256) {
                    int row = i >> 2, c8 = i & 3;
                    cpa16(sptr(bnxt + row*BC + c8*8), src + row*256 + c8*8);
                }
                CPA_COMMIT();
            }
            if (kc == 0) {
#pragma unroll
                for (int nb = 0; nb < 16; nb++) {
                    acc[nb][0]=0.f; acc[nb][1]=0.f; acc[nb][2]=0.f; acc[nb][3]=0.f;
                }
            }
#pragma unroll
            for (int kk = 0; kk < 2; kk++) {
                uint32_t A0[4];
                ldsm4(A0[0],A0[1],A0[2],A0[3],
                      sptr(xs + a_row*HSH + kc*32 + kk*16 + a_koff));
#pragma unroll
                for (int np = 0; np < 8; np++) {
                    int cb = np*16 + b_nrow;
                    uint32_t b0,b1r,b2,b3;
                    ldsm4(b0,b1r,b2,b3, sptr(bcur + cb*BC + kk*16 + b_koff));
                    mma_f16(acc[2*np][0],acc[2*np][1],acc[2*np][2],acc[2*np][3],
                            A0[0],A0[1],A0[2],A0[3], b0,b1r);
                    mma_f16(acc[2*np+1][0],acc[2*np+1][1],acc[2*np+1][2],acc[2*np+1][3],
                            A0[0],A0[1],A0[2],A0[3], b2,b3);
                }
            }
            if (kc == 7) {
#pragma unroll
                for (int nb = 0; nb < 16; nb++) {
                    int col = nc*128 + nb*8 + 2*t;
                    int rowa = wid*16 + g;
                    long gr = r0 + rowa;
                    *(__half2*)(&g_qkvh[gr*768 + col])     = __floats2half2_rn(acc[nb][0], acc[nb][1]);
                    *(__half2*)(&g_qkvh[(gr+8)*768 + col]) = __floats2half2_rn(acc[nb][2], acc[nb][3]);
                }
            }
        }
    }
}

/* ---------------- 7) attention (tensor-core, reg-prefetch heads) + proj ---------------- */
__global__ void __launch_bounds__(256, 1) k_attnproj(const float* __restrict__ projb,
                                                     float* __restrict__ out) {
    extern __shared__ __half smh[];
    __half* xs  = smh;                        /* 128 x HSH fp16 attn out */
    __half* bsm = smh + 128*HSH;              /* 2 x 256 x B2SH */
    __half* wbh = bsm + 2*256*B2SH;           /* 8 warps x 5 x 16 x ASH */
    int tid = threadIdx.x;
    int w = tid >> 5, lane = tid & 31;
    int g = lane >> 2, t = lane & 3;
    __half* qh = wbh + w*5*16*ASH;
    __half* kh = qh + 16*ASH;
    __half* kq = kh + 16*ASH;
    __half* ph = kq + 16*ASH;
    __half* vh = ph + 16*ASH;
    long row0 = (long)blockIdx.x*128 + w*16;
    int a_koff = (lane & 16) ? 8 : 0;
    int b_nrow = (lane & 7) + ((lane & 16) ? 8 : 0);
    int b_koff = (lane & 8) ? 8 : 0;
    int t_mrow = lane & 15;
    int t_doff = (lane & 16) ? 8 : 0;

    int p4 = lane & 3;
    int m0 = (lane >> 2);
    const __half* qrow0 = &g_qkvh[(row0 + m0)*768 + p4*8];
    const __half* qrow1 = &g_qkvh[(row0 + m0 + 8)*768 + p4*8];
    const __half* p0r0 = &g_posh[0][(row0 + m0)*256 + p4*8];
    const __half* p0r1 = &g_posh[0][(row0 + m0 + 8)*256 + p4*8];
    const __half* p1r0 = &g_posh[1][(row0 + m0)*256 + p4*8];
    const __half* p1r1 = &g_posh[1][(row0 + m0 + 8)*256 + p4*8];
    const __half* p2r0 = &g_posh[2][(row0 + m0)*256 + p4*8];
    const __half* p2r1 = &g_posh[2][(row0 + m0 + 8)*256 + p4*8];

    int4 pfq[2], pfk[2], pfv[2], pfpq[2], pfpk[2], pfpv[2];
    {
        pfq[0]  = *(const int4*)(qrow0);
        pfk[0]  = *(const int4*)(qrow0 + 256);
        pfv[0]  = *(const int4*)(qrow0 + 512);
        pfq[1]  = *(const int4*)(qrow1);
        pfk[1]  = *(const int4*)(qrow1 + 256);
        pfv[1]  = *(const int4*)(qrow1 + 512);
        pfpq[0] = *(const int4*)(p0r0);
        pfpq[1] = *(const int4*)(p0r1);
        pfpk[0] = *(const int4*)(p1r0);
        pfpk[1] = *(const int4*)(p1r1);
        pfpv[0] = *(const int4*)(p2r0);
        pfpv[1] = *(const int4*)(p2r1);
    }

    for (int h = 0; h < 8; h++) {
        int ho = h*32;
#pragma unroll
        for (int it = 0; it < 2; it++) {
            int m = it*8 + m0;
            *(int4*)(qh + m*ASH + p4*8) = pfq[it];
            *(int4*)(kh + m*ASH + p4*8) = pfk[it];
            *(int4*)(kq + m*ASH + p4*8) = hadd2x4(pfk[it], pfpq[it]);
            *(int4*)(ph + m*ASH + p4*8) = pfpk[it];
            *(int4*)(vh + m*ASH + p4*8) = hadd2x4(pfv[it], pfpv[it]);
        }
        __syncwarp();
        if (h < 7) {
            int hn = (h + 1)*32;
            pfq[0]  = *(const int4*)(qrow0 + hn);
            pfk[0]  = *(const int4*)(qrow0 + 256 + hn);
            pfv[0]  = *(const int4*)(qrow0 + 512 + hn);
            pfq[1]  = *(const int4*)(qrow1 + hn);
            pfk[1]  = *(const int4*)(qrow1 + 256 + hn);
            pfv[1]  = *(const int4*)(qrow1 + 512 + hn);
            pfpq[0] = *(const int4*)(p0r0 + hn);
            pfpq[1] = *(const int4*)(p0r1 + hn);
            pfpk[0] = *(const int4*)(p1r0 + hn);
            pfpk[1] = *(const int4*)(p1r1 + hn);
            pfpv[0] = *(const int4*)(p2r0 + hn);
            pfpv[1] = *(const int4*)(p2r1 + hn);
        }
        float c[2][4];
        c[0][0]=c[0][1]=c[0][2]=c[0][3]=0.f;
        c[1][0]=c[1][1]=c[1][2]=c[1][3]=0.f;
        int aa_row = lane & 15;
#pragma unroll
        for (int ks = 0; ks < 2; ks++) {
            uint32_t a0,a1,a2,a3, b0,b1r,b2,b3;
            ldsm4(a0,a1,a2,a3, sptr(qh + aa_row*ASH + ks*16 + a_koff));
            ldsm4(b0,b1r,b2,b3, sptr(kq + b_nrow*ASH + ks*16 + b_koff));
            mma_f16(c[0][0],c[0][1],c[0][2],c[0][3], a0,a1,a2,a3, b0,b1r);
            mma_f16(c[1][0],c[1][1],c[1][2],c[1][3], a0,a1,a2,a3, b2,b3);
            ldsm4(a0,a1,a2,a3, sptr(kh + aa_row*ASH + ks*16 + a_koff));
            ldsm4(b0,b1r,b2,b3, sptr(ph + b_nrow*ASH + ks*16 + b_koff));
            mma_f16(c[0][0],c[0][1],c[0][2],c[0][3], a0,a1,a2,a3, b0,b1r);
            mma_f16(c[1][0],c[1][1],c[1][2],c[1][3], a0,a1,a2,a3, b2,b3);
        }
        float mx0 = fmaxf(fmaxf(c[0][0], c[0][1]), fmaxf(c[1][0], c[1][1]));
        float mx1 = fmaxf(fmaxf(c[0][2], c[0][3]), fmaxf(c[1][2], c[1][3]));
        mx0 = fmaxf(mx0, __shfl_xor_sync(0xffffffffu, mx0, 1));
        mx0 = fmaxf(mx0, __shfl_xor_sync(0xffffffffu, mx0, 2));
        mx1 = fmaxf(mx1, __shfl_xor_sync(0xffffffffu, mx1, 1));
        mx1 = fmaxf(mx1, __shfl_xor_sync(0xffffffffu, mx1, 2));
        float e[2][4];
#pragma unroll
        for (int j = 0; j < 2; j++) {
            e[j][0] = __expf((c[j][0] - mx0) * ATT_SCALE);
            e[j][1] = __expf((c[j][1] - mx0) * ATT_SCALE);
            e[j][2] = __expf((c[j][2] - mx1) * ATT_SCALE);
            e[j][3] = __expf((c[j][3] - mx1) * ATT_SCALE);
        }
        float s0 = e[0][0] + e[0][1] + e[1][0] + e[1][1];
        float s1 = e[0][2] + e[0][3] + e[1][2] + e[1][3];
        s0 += __shfl_xor_sync(0xffffffffu, s0, 1);
        s0 += __shfl_xor_sync(0xffffffffu, s0, 2);
        s1 += __shfl_xor_sync(0xffffffffu, s1, 1);
        s1 += __shfl_xor_sync(0xffffffffu, s1, 2);
        float inv0 = 1.f / s0, inv1 = 1.f / s1;
        uint32_t pa0 = pack_h2(e[0][0]*inv0, e[0][1]*inv0);
        uint32_t pa1 = pack_h2(e[0][2]*inv1, e[0][3]*inv1);
        uint32_t pa2 = pack_h2(e[1][0]*inv0, e[1][1]*inv0);
        uint32_t pa3 = pack_h2(e[1][2]*inv1, e[1][3]*inv1);
        float o[4][4];
#pragma unroll
        for (int j = 0; j < 4; j++) { o[j][0]=o[j][1]=o[j][2]=o[j][3]=0.f; }
        {
            uint32_t b0,b1r,b2,b3;
            ldsm4t(b0,b1r,b2,b3, sptr(vh + t_mrow*ASH + t_doff));
            mma_f16(o[0][0],o[0][1],o[0][2],o[0][3], pa0,pa1,pa2,pa3, b0,b1r);
            mma_f16(o[1][0],o[1][1],o[1][2],o[1][3], pa0,pa1,pa2,pa3, b2,b3);
            ldsm4t(b0,b1r,b2,b3, sptr(vh + t_mrow*ASH + 16 + t_doff));
            mma_f16(o[2][0],o[2][1],o[2][2],o[2][3], pa0,pa1,pa2,pa3, b0,b1r);
            mma_f16(o[3][0],o[3][1],o[3][2],o[3][3], pa0,pa1,pa2,pa3, b2,b3);
        }
#pragma unroll
        for (int j = 0; j < 4; j++) {
            int col = ho + j*8 + 2*t;
            *(__half2*)(xs + (w*16 + g)*HSH + col)     = __floats2half2_rn(o[j][0], o[j][1]);
            *(__half2*)(xs + (w*16 + g + 8)*HSH + col) = __floats2half2_rn(o[j][2], o[j][3]);
        }
        __syncwarp();
    }
    __syncthreads();

    /* proj: [128x256]@[256x256] + proj_b ; warp = 32 rows x 128 cols */
    {
        int mg = w >> 1, nh = w & 1;
        int a_row = mg*32 + (lane & 15);
        float acc[2][16][4];
#pragma unroll
        for (int rt = 0; rt < 2; rt++)
#pragma unroll
            for (int nb = 0; nb < 16; nb++) {
                acc[rt][nb][0]=0.f; acc[rt][nb][1]=0.f; acc[rt][nb][2]=0.f; acc[rt][nb][3]=0.f;
            }
        for (int kc = 0; kc < 4; kc++) {
            if (kc == 0) {
                for (int i = tid; i < 256*8; i += 256) {
                    int row = i >> 3, c8 = i & 7;
                    cpa16(sptr(bsm + row*B2SH + c8*8), g_projh + row*256 + c8*8);
                }
                CPA_COMMIT(); CPA_WAIT0();
                __syncthreads();
            }
            __half* bcur = bsm + (kc & 1)*256*B2SH;
            if (kc < 3) {
                __half* bnxt = bsm + ((kc + 1) & 1)*256*B2SH;
                for (int i = tid; i < 256*8; i += 256) {
                    int row = i >> 3, c8 = i & 7;
                    cpa16(sptr(bnxt + row*B2SH + c8*8), g_projh + row*256 + (kc+1)*64 + c8*8);
                }
                CPA_COMMIT();
            }
#pragma unroll
            for (int kk = 0; kk < 4; kk++) {
                uint32_t A0[4], A1[4];
                ldsm4(A0[0],A0[1],A0[2],A0[3], sptr(xs + a_row*HSH + kc*64 + kk*16 + a_koff));
                ldsm4(A1[0],A1[1],A1[2],A1[3], sptr(xs + (a_row+16)*HSH + kc*64 + kk*16 + a_koff));
#pragma unroll
                for (int np = 0; np < 8; np++) {
                    int cb = nh*128 + np*16 + b_nrow;
                    uint32_t b0,b1r,b2,b3;
                    ldsm4(b0,b1r,b2,b3, sptr(bcur + cb*B2SH + kk*16 + b_koff));
                    mma_f16(acc[0][2*np][0],acc[0][2*np][1],acc[0][2*np][2],acc[0][2*np][3],
                            A0[0],A0[1],A0[2],A0[3], b0,b1r);
                    mma_f16(acc[0][2*np+1][0],acc[0][2*np+1][1],acc[0][2*np+1][2],acc[0][2*np+1][3],
                            A0[0],A0[1],A0[2],A0[3], b2,b3);
                    mma_f16(acc[1][2*np][0],acc[1][2*np][1],acc[1][2*np][2],acc[1][2*np][3],
                            A1[0],A1[1],A1[2],A1[3], b0,b1r);
                    mma_f16(acc[1][2*np+1][0],acc[1][2*np+1][1],acc[1][2*np+1][2],acc[1][2*np+1][3],
                            A1[0],A1[1],A1[2],A1[3], b2,b3);
                }
            }
            CPA_WAIT0();
            __syncthreads();
        }
#pragma unroll
        for (int rt = 0; rt < 2; rt++)
#pragma unroll
            for (int nb = 0; nb < 16; nb++) {
                int col = nh*128 + nb*8 + 2*t;
                int rowa = mg*32 + rt*16 + g;
                float bb0 = __ldg(&projb[col]), bb1 = __ldg(&projb[col+1]);
                long gr = (long)blockIdx.x*128 + rowa;
                *(float2*)(&out[gr*DIM + col])     = make_float2(acc[rt][nb][0]+bb0, acc[rt][nb][1]+bb1);
                *(float2*)(&out[(gr+8)*DIM + col]) = make_float2(acc[rt][nb][2]+bb0, acc[rt][nb][3]+bb1);
            }
    }
}

/* ---------------- launcher ---------------- */
extern "C" void kernel_launch(void* const* d_in, const int* in_sizes, int n_in,
                              void* d_out, int out_size) {
    (void)in_sizes; (void)n_in; (void)out_size;
    const float* x     = (const float*)d_in[0];
    const float* pr    = (const float*)d_in[1];
    const float* qkvw  = (const float*)d_in[2];
    const float* projw = (const float*)d_in[3];
    const float* projb = (const float*)d_in[4];
    const float* qw1 = (const float*)d_in[5];
    const float* qb1 = (const float*)d_in[6];
    const float* qg  = (const float*)d_in[7];
    const float* qbe = (const float*)d_in[8];
    const float* qw2 = (const float*)d_in[9];
    const float* qb2 = (const float*)d_in[10];
    const float* kw1 = (const float*)d_in[11];
    const float* kb1 = (const float*)d_in[12];
    const float* kg  = (const float*)d_in[13];
    const float* kbe = (const float*)d_in[14];
    const float* kw2 = (const float*)d_in[15];
    const float* kb2 = (const float*)d_in[16];
    const float* vw1 = (const float*)d_in[17];
    const float* vb1 = (const float*)d_in[18];
    const float* vg  = (const float*)d_in[19];
    const float* vbe = (const float*)d_in[20];
    const float* vw2 = (const float*)d_in[21];
    const float* vb2 = (const float*)d_in[22];

    const int smem_mlpqkv = (BSM_OFF + 2*128*BC) * 2;               /* 102400 B */
    const int smem_ap     = (128*HSH + 2*256*B2SH + 8*5*16*ASH) * 2;/* 192512 B */
    cudaFuncSetAttribute(k_mlpqkv,   cudaFuncAttributeMaxDynamicSharedMemorySize, smem_mlpqkv);
    cudaFuncSetAttribute(k_attnproj, cudaFuncAttributeMaxDynamicSharedMemorySize, smem_ap);

    k_stats_part<<<256, 256>>>(pr);
    k_stats_red<<<10, 256>>>();
    k_prep<<<224, 512>>>(qkvw, qw2, kw2, vw2, projw);
    k_fold<<<96, 256>>>(qw1, qb1, qg, qbe, kw1, kb1, kg, kbe, vw1, vb1, vg, vbe);
    k_mlpqkv<<<2048, 256, smem_mlpqkv>>>(pr, qb2, kb2, vb2, x);
    k_attnproj<<<NROWS/128, 256, smem_ap>>>(projb, (float*)d_out);
}

// round 14
// speedup vs baseline: 1.0688x; 1.0688x over previous
#include <cuda_runtime.h>
#include <cuda_fp16.h>
#include <stdint.h>
#include <math.h>

#define NBATCH 8192
#define NS 16
#define DIM 256
#define PF 48
#define NROWS (NBATCH*NS)   /* 131072 */
#define EPSC 1e-5f
#define ATT_SCALE 0.17677669529663687f
#define PSH 56    /* prs stride (halves) */
#define HSH 264   /* 256-col fp16 A tile stride (halves) */
#define B1SH 56   /* layer1 B stride */
#define B2SH 72   /* 64-k chunk stride (mlpqkv) */
#define BC 40     /* 32-k chunk stride (attnproj proj) */
#define ASH 40    /* v tile stride */
#define QKS 72    /* concat q|k and kq|pk tile stride */

/* ---------------- device scratch ---------------- */
__device__ float g_part_S[256][PF*PF];
__device__ float g_part_m[256][PF];
__device__ float g_S[PF*PF];
__device__ float g_m[PF];
__device__ __half g_w1h[3][256*PF];
__device__ float  g_b1e[3][DIM];
__device__ __half g_qkvwh[768*256];
__device__ __half g_w2h[3][256*256];
__device__ __half g_projh[256*256];
__device__ __half g_posh[3][(long)NROWS*256];
__device__ __half g_qkvh[(long)NROWS*768];

/* ---------------- helpers ---------------- */
__device__ __forceinline__ void mma_f16(float& c0, float& c1, float& c2, float& c3,
                                        uint32_t a0, uint32_t a1, uint32_t a2, uint32_t a3,
                                        uint32_t b0, uint32_t b1) {
    asm volatile("mma.sync.aligned.m16n8k16.row.col.f32.f16.f16.f32 "
                 "{%0,%1,%2,%3},{%4,%5,%6,%7},{%8,%9},{%0,%1,%2,%3};"
                 : "+f"(c0), "+f"(c1), "+f"(c2), "+f"(c3)
                 : "r"(a0), "r"(a1), "r"(a2), "r"(a3), "r"(b0), "r"(b1));
}
__device__ __forceinline__ uint32_t sptr(const void* p) {
    return (uint32_t)__cvta_generic_to_shared(p);
}
__device__ __forceinline__ void ldsm4(uint32_t& r0, uint32_t& r1, uint32_t& r2, uint32_t& r3,
                                      uint32_t addr) {
    asm volatile("ldmatrix.sync.aligned.m8n8.x4.shared.b16 {%0,%1,%2,%3}, [%4];"
                 : "=r"(r0), "=r"(r1), "=r"(r2), "=r"(r3) : "r"(addr));
}
__device__ __forceinline__ void ldsm4t(uint32_t& r0, uint32_t& r1, uint32_t& r2, uint32_t& r3,
                                       uint32_t addr) {
    asm volatile("ldmatrix.sync.aligned.m8n8.x4.trans.shared.b16 {%0,%1,%2,%3}, [%4];"
                 : "=r"(r0), "=r"(r1), "=r"(r2), "=r"(r3) : "r"(addr));
}
__device__ __forceinline__ uint32_t h2_as_u32(__half2 h) {
    uint32_t u;
    __builtin_memcpy(&u, &h, 4);
    return u;
}
__device__ __forceinline__ __half2 u32_as_h2(uint32_t u) {
    __half2 h;
    __builtin_memcpy(&h, &u, 4);
    return h;
}
__device__ __forceinline__ uint32_t pack_h2(float a, float b) {
    return h2_as_u32(__floats2half2_rn(a, b));
}
__device__ __forceinline__ int4 hadd2x4(int4 a, int4 b) {
    int4 r;
    r.x = (int)h2_as_u32(__hadd2(u32_as_h2((uint32_t)a.x), u32_as_h2((uint32_t)b.x)));
    r.y = (int)h2_as_u32(__hadd2(u32_as_h2((uint32_t)a.y), u32_as_h2((uint32_t)b.y)));
    r.z = (int)h2_as_u32(__hadd2(u32_as_h2((uint32_t)a.z), u32_as_h2((uint32_t)b.z)));
    r.w = (int)h2_as_u32(__hadd2(u32_as_h2((uint32_t)a.w), u32_as_h2((uint32_t)b.w)));
    return r;
}
__device__ __forceinline__ void cpa16(uint32_t dst, const void* src) {
    asm volatile("cp.async.cg.shared.global [%0], [%1], 16;" :: "r"(dst), "l"(src));
}
#define CPA_COMMIT() asm volatile("cp.async.commit_group;" ::: "memory")
#define CPA_WAIT0()  asm volatile("cp.async.wait_group 0;" ::: "memory")

/* ---------------- 1) partial stats ---------------- */
__global__ void k_stats_part(const float* __restrict__ pr) {
    __shared__ float ps[64*PF];
    int tid = threadIdx.x;
    int ti = tid >> 4, tj = tid & 15;
    float acc[9]; float asum[3];
#pragma unroll
    for (int i = 0; i < 9; i++) acc[i] = 0.f;
    asum[0] = asum[1] = asum[2] = 0.f;
    int r0 = blockIdx.x * 512;
    for (int t = 0; t < 8; t++) {
        const float* src = pr + (long)(r0 + t*64) * PF;
        for (int i = tid; i < 64*PF; i += 256) ps[i] = src[i];
        __syncthreads();
        for (int r = 0; r < 64; r++) {
            float si0 = ps[r*PF + 3*ti + 0];
            float si1 = ps[r*PF + 3*ti + 1];
            float si2 = ps[r*PF + 3*ti + 2];
            float sj0 = ps[r*PF + 3*tj + 0];
            float sj1 = ps[r*PF + 3*tj + 1];
            float sj2 = ps[r*PF + 3*tj + 2];
            acc[0] += si0*sj0; acc[1] += si0*sj1; acc[2] += si0*sj2;
            acc[3] += si1*sj0; acc[4] += si1*sj1; acc[5] += si1*sj2;
            acc[6] += si2*sj0; acc[7] += si2*sj1; acc[8] += si2*sj2;
            if (tj == 0) { asum[0] += si0; asum[1] += si1; asum[2] += si2; }
        }
        __syncthreads();
    }
#pragma unroll
    for (int a = 0; a < 3; a++)
#pragma unroll
        for (int bq = 0; bq < 3; bq++)
            g_part_S[blockIdx.x][(3*ti + a)*PF + 3*tj + bq] = acc[a*3 + bq];
    if (tj == 0) {
        g_part_m[blockIdx.x][3*ti + 0] = asum[0];
        g_part_m[blockIdx.x][3*ti + 1] = asum[1];
        g_part_m[blockIdx.x][3*ti + 2] = asum[2];
    }
}

/* ---------------- 2) final reduce ---------------- */
__global__ void k_stats_red() {
    int i = blockIdx.x * 256 + threadIdx.x;
    if (i < PF*PF) {
        float s = 0.f;
        for (int c = 0; c < 256; c++) s += g_part_S[c][i];
        g_S[i] = s;
    } else if (i < PF*PF + PF) {
        int j = i - PF*PF;
        float s = 0.f;
        for (int c = 0; c < 256; c++) s += g_part_m[c][j];
        g_m[j] = s * (1.f / (float)NROWS);
    }
}

/* ---------------- 3) fp32 -> fp16 weight convert ---------------- */
__global__ void k_prep(const float* __restrict__ qkvw, const float* __restrict__ w2q,
                       const float* __restrict__ w2k, const float* __restrict__ w2v,
                       const float* __restrict__ projw) {
    int i4 = blockIdx.x * blockDim.x + threadIdx.x;
    const int N0 = 768*256/4;
    const int N1 = N0 + 3*65536/4;
    const int NT = N1 + 65536/4;
    if (i4 >= NT) return;
    const float* src; __half* dst; int j;
    if (i4 < N0) { src = qkvw; dst = g_qkvwh; j = i4; }
    else if (i4 < N1) {
        j = i4 - N0;
        int p = j / 16384; j -= p * 16384;
        src = (p == 0 ? w2q : (p == 1 ? w2k : w2v));
        dst = g_w2h[p];
    } else { src = projw; dst = g_projh; j = i4 - N1; }
    float4 v = *(const float4*)(src + j*4);
    __half2* d = (__half2*)(dst + j*4);
    d[0] = __floats2half2_rn(v.x, v.y);
    d[1] = __floats2half2_rn(v.z, v.w);
}

/* ---------------- 4) fold BN into layer-1 affine ---------------- */
__global__ void k_fold(const float* __restrict__ qw1, const float* __restrict__ qb1,
                       const float* __restrict__ qg,  const float* __restrict__ qbe,
                       const float* __restrict__ kw1, const float* __restrict__ kb1,
                       const float* __restrict__ kg,  const float* __restrict__ kbe,
                       const float* __restrict__ vw1, const float* __restrict__ vb1,
                       const float* __restrict__ vg,  const float* __restrict__ vbe) {
    __shared__ float ws[8][PF];
    int tid = threadIdx.x;
    int wl = tid >> 5, lane = tid & 31;
    int ch = blockIdx.x * 8 + wl;
    int p = ch >> 8, c = ch & 255;
    const float* w1 = (p == 0 ? qw1 : (p == 1 ? kw1 : vw1)) + c*PF;
    const float* b1 = (p == 0 ? qb1 : (p == 1 ? kb1 : vb1));
    const float* gg = (p == 0 ? qg  : (p == 1 ? kg  : vg ));
    const float* be = (p == 0 ? qbe : (p == 1 ? kbe : vbe));
    ws[wl][lane] = w1[lane];
    if (lane < PF - 32) ws[wl][lane + 32] = w1[lane + 32];
    __syncwarp();
    float quad = 0.f, wm = 0.f;
#pragma unroll
    for (int ii = 0; ii < 2; ii++) {
        int i = lane + ii*32;
        if (i < PF) {
            float wi = ws[wl][i];
            float t = 0.f;
            for (int j = 0; j < PF; j++) t += g_S[i*PF + j] * ws[wl][j];
            quad += wi * t;
            wm   += wi * g_m[i];
        }
    }
    for (int off = 16; off > 0; off >>= 1) {
        quad += __shfl_xor_sync(0xffffffffu, quad, off);
        wm   += __shfl_xor_sync(0xffffffffu, wm,   off);
    }
    float var   = quad * (1.f / (float)NROWS) - wm * wm;
    float scale = gg[c] * rsqrtf(var + EPSC);
    float mu    = wm + b1[c];
    float b1e   = (b1[c] - mu) * scale + be[c];
#pragma unroll
    for (int ii = 0; ii < 2; ii++) {
        int j = lane + ii*32;
        if (j < PF) g_w1h[p][c*PF + j] = __float2half(ws[wl][j] * scale);
    }
    if (lane == 0) g_b1e[p][c] = b1e;
}

/* ---------------- 5) merged pos-MLPs + qkv GEMM (round-12 version, grid 1024) ---- */
#define BSM_OFF (256*PSH + 256*HSH)
__global__ void __launch_bounds__(256, 1) k_mlpqkv(const float* __restrict__ pr,
        const float* __restrict__ qb2, const float* __restrict__ kb2,
        const float* __restrict__ vb2, const float* __restrict__ x) {
    extern __shared__ __half smh[];
    __half* bsm = smh + BSM_OFF;              /* 2 x 128 x B2SH */
    int tid = threadIdx.x;
    int wid = tid >> 5, lane = tid & 31;
    int g = lane >> 2, t = lane & 3;
    int mg = wid;
    int a_row = mg*32 + (lane & 15);
    int a_koff = (lane & 16) ? 8 : 0;
    int b_nrow = (lane & 7) + ((lane & 16) ? 8 : 0);
    int b_koff = (lane & 8) ? 8 : 0;

    if (blockIdx.x < 512) {
        /* ================= posmlp branch ================= */
        __half* prs = smh;
        __half* hs  = smh + 256*PSH;
        int r0 = blockIdx.x * 256;

        for (int i = tid; i < 256*12; i += 256) {
            int row = i / 12, c4 = i % 12;
            float4 v = *(const float4*)(pr + (long)(r0 + row)*PF + c4*4);
            __half2* d = (__half2*)(prs + row*PSH + c4*4);
            d[0] = __floats2half2_rn(v.x, v.y);
            d[1] = __floats2half2_rn(v.z, v.w);
        }
        __syncthreads();

        for (int p = 0; p < 3; p++) {
            for (int i = tid; i < 256*6; i += 256) {
                int row = i / 6, c8 = i % 6;
                cpa16(sptr(bsm + row*B1SH + c8*8), g_w1h[p] + row*PF + c8*8);
            }
            CPA_COMMIT(); CPA_WAIT0();
            __syncthreads();
            const float* b1 = g_b1e[p];
            for (int nc = 0; nc < 2; nc++) {
                float acc[2][16][4];
#pragma unroll
                for (int rt = 0; rt < 2; rt++)
#pragma unroll
                    for (int nb = 0; nb < 16; nb++) {
                        acc[rt][nb][0]=0.f; acc[rt][nb][1]=0.f; acc[rt][nb][2]=0.f; acc[rt][nb][3]=0.f;
                    }
#pragma unroll
                for (int ks = 0; ks < 3; ks++) {
                    uint32_t A0[4], A1[4];
                    ldsm4(A0[0],A0[1],A0[2],A0[3], sptr(prs + a_row*PSH + ks*16 + a_koff));
                    ldsm4(A1[0],A1[1],A1[2],A1[3], sptr(prs + (a_row+16)*PSH + ks*16 + a_koff));
#pragma unroll
                    for (int np = 0; np < 8; np++) {
                        int cb = nc*128 + np*16 + b_nrow;
                        uint32_t b0,b1r,b2,b3;
                        ldsm4(b0,b1r,b2,b3, sptr(bsm + cb*B1SH + ks*16 + b_koff));
                        mma_f16(acc[0][2*np][0],acc[0][2*np][1],acc[0][2*np][2],acc[0][2*np][3],
                                A0[0],A0[1],A0[2],A0[3], b0,b1r);
                        mma_f16(acc[0][2*np+1][0],acc[0][2*np+1][1],acc[0][2*np+1][2],acc[0][2*np+1][3],
                                A0[0],A0[1],A0[2],A0[3], b2,b3);
                        mma_f16(acc[1][2*np][0],acc[1][2*np][1],acc[1][2*np][2],acc[1][2*np][3],
                                A1[0],A1[1],A1[2],A1[3], b0,b1r);
                        mma_f16(acc[1][2*np+1][0],acc[1][2*np+1][1],acc[1][2*np+1][2],acc[1][2*np+1][3],
                                A1[0],A1[1],A1[2],A1[3], b2,b3);
                    }
                }
#pragma unroll
                for (int rt = 0; rt < 2; rt++)
#pragma unroll
                    for (int nb = 0; nb < 16; nb++) {
                        int col = nc*128 + nb*8 + 2*t;
                        int rowa = mg*32 + rt*16 + g;
                        float bb0 = __ldg(&b1[col]), bb1 = __ldg(&b1[col+1]);
                        *(__half2*)(hs + rowa*HSH + col) =
                            __floats2half2_rn(fmaxf(acc[rt][nb][0]+bb0, 0.f), fmaxf(acc[rt][nb][1]+bb1, 0.f));
                        *(__half2*)(hs + (rowa+8)*HSH + col) =
                            __floats2half2_rn(fmaxf(acc[rt][nb][2]+bb0, 0.f), fmaxf(acc[rt][nb][3]+bb1, 0.f));
                    }
            }
            __syncthreads();
            const float* b2 = (p == 0 ? qb2 : (p == 1 ? kb2 : vb2));
            for (int i = tid; i < 128*8; i += 256) {
                int row = i >> 3, c8 = i & 7;
                cpa16(sptr(bsm + row*B2SH + c8*8), g_w2h[p] + row*256 + c8*8);
            }
            CPA_COMMIT();
            float acc[2][16][4];
            for (int c = 0; c < 8; c++) {
                int nc = c >> 2, kc = c & 3;
                __half* bcur = bsm + (c & 1)*128*B2SH;
                CPA_WAIT0();
                __syncthreads();
                if (c < 7) {
                    int cn = c + 1;
                    __half* bnxt = bsm + (cn & 1)*128*B2SH;
                    const __half* src = g_w2h[p] + (long)((cn >> 2)*128)*256 + (cn & 3)*64;
                    for (int i = tid; i < 128*8; i += 256) {
                        int row = i >> 3, c8 = i & 7;
                        cpa16(sptr(bnxt + row*B2SH + c8*8), src + row*256 + c8*8);
                    }
                    CPA_COMMIT();
                }
                if (kc == 0) {
#pragma unroll
                    for (int rt = 0; rt < 2; rt++)
#pragma unroll
                        for (int nb = 0; nb < 16; nb++) {
                            acc[rt][nb][0]=0.f; acc[rt][nb][1]=0.f; acc[rt][nb][2]=0.f; acc[rt][nb][3]=0.f;
                        }
                }
#pragma unroll
                for (int kk = 0; kk < 4; kk++) {
                    uint32_t A0[4], A1[4];
                    ldsm4(A0[0],A0[1],A0[2],A0[3], sptr(hs + a_row*HSH + kc*64 + kk*16 + a_koff));
                    ldsm4(A1[0],A1[1],A1[2],A1[3], sptr(hs + (a_row+16)*HSH + kc*64 + kk*16 + a_koff));
#pragma unroll
                    for (int np = 0; np < 8; np++) {
                        int cb = np*16 + b_nrow;
                        uint32_t b0,b1r,b2,b3;
                        ldsm4(b0,b1r,b2,b3, sptr(bcur + cb*B2SH + kk*16 + b_koff));
                        mma_f16(acc[0][2*np][0],acc[0][2*np][1],acc[0][2*np][2],acc[0][2*np][3],
                                A0[0],A0[1],A0[2],A0[3], b0,b1r);
                        mma_f16(acc[0][2*np+1][0],acc[0][2*np+1][1],acc[0][2*np+1][2],acc[0][2*np+1][3],
                                A0[0],A0[1],A0[2],A0[3], b2,b3);
                        mma_f16(acc[1][2*np][0],acc[1][2*np][1],acc[1][2*np][2],acc[1][2*np][3],
                                A1[0],A1[1],A1[2],A1[3], b0,b1r);
                        mma_f16(acc[1][2*np+1][0],acc[1][2*np+1][1],acc[1][2*np+1][2],acc[1][2*np+1][3],
                                A1[0],A1[1],A1[2],A1[3], b2,b3);
                    }
                }
                if (kc == 3) {
#pragma unroll
                    for (int rt = 0; rt < 2; rt++)
#pragma unroll
                        for (int nb = 0; nb < 16; nb++) {
                            int col = nc*128 + nb*8 + 2*t;
                            int rowa = mg*32 + rt*16 + g;
                            float bb0 = __ldg(&b2[col]), bb1 = __ldg(&b2[col+1]);
                            long gr = r0 + rowa;
                            *(__half2*)(&g_posh[p][gr*256 + col]) =
                                __floats2half2_rn(acc[rt][nb][0]+bb0, acc[rt][nb][1]+bb1);
                            *(__half2*)(&g_posh[p][(gr+8)*256 + col]) =
                                __floats2half2_rn(acc[rt][nb][2]+bb0, acc[rt][nb][3]+bb1);
                        }
                }
            }
            __syncthreads();
        }
    } else {
        /* ================= qkv branch: 24 continuous chunks ================= */
        __half* xs = smh;
        int r0 = (blockIdx.x - 512) * 256;

        for (int i = tid; i < 256*64; i += 256) {
            int row = i >> 6, c4 = i & 63;
            float4 v = *(const float4*)(x + (long)(r0 + row)*DIM + c4*4);
            __half2* d = (__half2*)(xs + row*HSH + c4*4);
            d[0] = __floats2half2_rn(v.x, v.y);
            d[1] = __floats2half2_rn(v.z, v.w);
        }
        for (int i = tid; i < 128*8; i += 256) {
            int row = i >> 3, c8 = i & 7;
            cpa16(sptr(bsm + row*B2SH + c8*8), g_qkvwh + row*256 + c8*8);
        }
        CPA_COMMIT();
        __syncthreads();

        float acc[2][16][4];
        for (int c = 0; c < 24; c++) {
            int nc = c >> 2, kc = c & 3;
            __half* bcur = bsm + (c & 1)*128*B2SH;
            CPA_WAIT0();
            __syncthreads();
            if (c < 23) {
                int cn = c + 1;
                __half* bnxt = bsm + (cn & 1)*128*B2SH;
                const __half* src = g_qkvwh + (long)((cn >> 2)*128)*256 + (cn & 3)*64;
                for (int i = tid; i < 128*8; i += 256) {
                    int row = i >> 3, c8 = i & 7;
                    cpa16(sptr(bnxt + row*B2SH + c8*8), src + row*256 + c8*8);
                }
                CPA_COMMIT();
            }
            if (kc == 0) {
#pragma unroll
                for (int rt = 0; rt < 2; rt++)
#pragma unroll
                    for (int nb = 0; nb < 16; nb++) {
                        acc[rt][nb][0]=0.f; acc[rt][nb][1]=0.f; acc[rt][nb][2]=0.f; acc[rt][nb][3]=0.f;
                    }
            }
#pragma unroll
            for (int kk = 0; kk < 4; kk++) {
                uint32_t A0[4], A1[4];
                ldsm4(A0[0],A0[1],A0[2],A0[3], sptr(xs + a_row*HSH + kc*64 + kk*16 + a_koff));
                ldsm4(A1[0],A1[1],A1[2],A1[3], sptr(xs + (a_row+16)*HSH + kc*64 + kk*16 + a_koff));
#pragma unroll
                for (int np = 0; np < 8; np++) {
                    int cb = np*16 + b_nrow;
                    uint32_t b0,b1r,b2,b3;
                    ldsm4(b0,b1r,b2,b3, sptr(bcur + cb*B2SH + kk*16 + b_koff));
                    mma_f16(acc[0][2*np][0],acc[0][2*np][1],acc[0][2*np][2],acc[0][2*np][3],
                            A0[0],A0[1],A0[2],A0[3], b0,b1r);
                    mma_f16(acc[0][2*np+1][0],acc[0][2*np+1][1],acc[0][2*np+1][2],acc[0][2*np+1][3],
                            A0[0],A0[1],A0[2],A0[3], b2,b3);
                    mma_f16(acc[1][2*np][0],acc[1][2*np][1],acc[1][2*np][2],acc[1][2*np][3],
                            A1[0],A1[1],A1[2],A1[3], b0,b1r);
                    mma_f16(acc[1][2*np+1][0],acc[1][2*np+1][1],acc[1][2*np+1][2],acc[1][2*np+1][3],
                            A1[0],A1[1],A1[2],A1[3], b2,b3);
                }
            }
            if (kc == 3) {
#pragma unroll
                for (int rt = 0; rt < 2; rt++)
#pragma unroll
                    for (int nb = 0; nb < 16; nb++) {
                        int col = nc*128 + nb*8 + 2*t;
                        int rowa = mg*32 + rt*16 + g;
                        long gr = r0 + rowa;
                        *(__half2*)(&g_qkvh[gr*768 + col])     = __floats2half2_rn(acc[rt][nb][0], acc[rt][nb][1]);
                        *(__half2*)(&g_qkvh[(gr+8)*768 + col]) = __floats2half2_rn(acc[rt][nb][2], acc[rt][nb][3]);
                    }
            }
        }
    }
}

/* ---------------- 7) attention + proj : 64 rows/CTA, 2 CTAs/SM ----------------
   smem: xs[64*HSH] | region shared between attention scratch and proj B bufs   */
#define AP_REGION (64*HSH)
__global__ void __launch_bounds__(256, 2) k_attnproj(const float* __restrict__ projb,
                                                     float* __restrict__ out) {
    extern __shared__ __half smh[];
    __half* xs  = smh;                        /* 64 x HSH fp16 attn out */
    __half* wbh = smh + AP_REGION;            /* 8 warps x (2x16xQKS + 16xASH) */
    __half* bsm = smh + AP_REGION;            /* proj: 2 x 256 x BC (aliases wbh) */
    int tid = threadIdx.x;
    int w = tid >> 5, lane = tid & 31;
    int g = lane >> 2, t = lane & 3;
    __half* qk = wbh + w*(2*16*QKS + 16*ASH);
    __half* kp = qk + 16*QKS;
    __half* vh = kp + 16*QKS;
    int b_loc = w >> 1;                       /* local batch 0..3 (16 rows each) */
    int hb = (w & 1) * 4;                     /* head base: 0 or 4 */
    long rowb = (long)blockIdx.x*64 + b_loc*16;
    int a_koff = (lane & 16) ? 8 : 0;
    int b_nrow = (lane & 7) + ((lane & 16) ? 8 : 0);
    int b_koff = (lane & 8) ? 8 : 0;
    int t_mrow = lane & 15;
    int t_doff = (lane & 16) ? 8 : 0;

    /* register prefetch pipeline over this warp's 4 heads */
    int p4 = lane & 3;
    int m0 = (lane >> 2);
    const __half* qrow0 = &g_qkvh[(rowb + m0)*768 + hb*32 + p4*8];
    const __half* qrow1 = &g_qkvh[(rowb + m0 + 8)*768 + hb*32 + p4*8];
    const __half* p0r0 = &g_posh[0][(rowb + m0)*256 + hb*32 + p4*8];
    const __half* p0r1 = &g_posh[0][(rowb + m0 + 8)*256 + hb*32 + p4*8];
    const __half* p1r0 = &g_posh[1][(rowb + m0)*256 + hb*32 + p4*8];
    const __half* p1r1 = &g_posh[1][(rowb + m0 + 8)*256 + hb*32 + p4*8];
    const __half* p2r0 = &g_posh[2][(rowb + m0)*256 + hb*32 + p4*8];
    const __half* p2r1 = &g_posh[2][(rowb + m0 + 8)*256 + hb*32 + p4*8];

    int4 pfq[2], pfk[2], pfv[2], pfpq[2], pfpk[2], pfpv[2];
    {
        pfq[0]  = *(const int4*)(qrow0);
        pfk[0]  = *(const int4*)(qrow0 + 256);
        pfv[0]  = *(const int4*)(qrow0 + 512);
        pfq[1]  = *(const int4*)(qrow1);
        pfk[1]  = *(const int4*)(qrow1 + 256);
        pfv[1]  = *(const int4*)(qrow1 + 512);
        pfpq[0] = *(const int4*)(p0r0);
        pfpq[1] = *(const int4*)(p0r1);
        pfpk[0] = *(const int4*)(p1r0);
        pfpk[1] = *(const int4*)(p1r1);
        pfpv[0] = *(const int4*)(p2r0);
        pfpv[1] = *(const int4*)(p2r1);
    }

    for (int hh = 0; hh < 4; hh++) {
        int h = hb + hh;
        int ho = h*32;
        /* stage combined tiles: qk=[q|k], kp=[k+pq|pk], vh=v+pv */
#pragma unroll
        for (int it = 0; it < 2; it++) {
            int m = it*8 + m0;
            *(int4*)(qk + m*QKS + p4*8)      = pfq[it];
            *(int4*)(qk + m*QKS + 32 + p4*8) = pfk[it];
            *(int4*)(kp + m*QKS + p4*8)      = hadd2x4(pfk[it], pfpq[it]);
            *(int4*)(kp + m*QKS + 32 + p4*8) = pfpk[it];
            *(int4*)(vh + m*ASH + p4*8)      = hadd2x4(pfv[it], pfpv[it]);
        }
        __syncwarp();
        if (hh < 3) {
            int hn = (hh + 1)*32;
            pfq[0]  = *(const int4*)(qrow0 + hn);
            pfk[0]  = *(const int4*)(qrow0 + 256 + hn);
            pfv[0]  = *(const int4*)(qrow0 + 512 + hn);
            pfq[1]  = *(const int4*)(qrow1 + hn);
            pfk[1]  = *(const int4*)(qrow1 + 256 + hn);
            pfv[1]  = *(const int4*)(qrow1 + 512 + hn);
            pfpq[0] = *(const int4*)(p0r0 + hn);
            pfpq[1] = *(const int4*)(p0r1 + hn);
            pfpk[0] = *(const int4*)(p1r0 + hn);
            pfpk[1] = *(const int4*)(p1r1 + hn);
            pfpv[0] = *(const int4*)(p2r0 + hn);
            pfpv[1] = *(const int4*)(p2r1 + hn);
        }
        /* dots = q@(k+pq)^T + k@pk^T, in the exact round-12 k-order:
           ks0: term1 k0-15, term2 k0-15; ks1: term1 k16-31, term2 k16-31 */
        float c[2][4];
        c[0][0]=c[0][1]=c[0][2]=c[0][3]=0.f;
        c[1][0]=c[1][1]=c[1][2]=c[1][3]=0.f;
        int aa_row = lane & 15;
#pragma unroll
        for (int ks = 0; ks < 2; ks++) {
            uint32_t a0,a1,a2,a3, b0,b1r,b2,b3;
            ldsm4(a0,a1,a2,a3, sptr(qk + aa_row*QKS + ks*16 + a_koff));
            ldsm4(b0,b1r,b2,b3, sptr(kp + b_nrow*QKS + ks*16 + b_koff));
            mma_f16(c[0][0],c[0][1],c[0][2],c[0][3], a0,a1,a2,a3, b0,b1r);
            mma_f16(c[1][0],c[1][1],c[1][2],c[1][3], a0,a1,a2,a3, b2,b3);
            ldsm4(a0,a1,a2,a3, sptr(qk + aa_row*QKS + 32 + ks*16 + a_koff));
            ldsm4(b0,b1r,b2,b3, sptr(kp + b_nrow*QKS + 32 + ks*16 + b_koff));
            mma_f16(c[0][0],c[0][1],c[0][2],c[0][3], a0,a1,a2,a3, b0,b1r);
            mma_f16(c[1][0],c[1][1],c[1][2],c[1][3], a0,a1,a2,a3, b2,b3);
        }
        float mx0 = fmaxf(fmaxf(c[0][0], c[0][1]), fmaxf(c[1][0], c[1][1]));
        float mx1 = fmaxf(fmaxf(c[0][2], c[0][3]), fmaxf(c[1][2], c[1][3]));
        mx0 = fmaxf(mx0, __shfl_xor_sync(0xffffffffu, mx0, 1));
        mx0 = fmaxf(mx0, __shfl_xor_sync(0xffffffffu, mx0, 2));
        mx1 = fmaxf(mx1, __shfl_xor_sync(0xffffffffu, mx1, 1));
        mx1 = fmaxf(mx1, __shfl_xor_sync(0xffffffffu, mx1, 2));
        float e[2][4];
#pragma unroll
        for (int j = 0; j < 2; j++) {
            e[j][0] = __expf((c[j][0] - mx0) * ATT_SCALE);
            e[j][1] = __expf((c[j][1] - mx0) * ATT_SCALE);
            e[j][2] = __expf((c[j][2] - mx1) * ATT_SCALE);
            e[j][3] = __expf((c[j][3] - mx1) * ATT_SCALE);
        }
        float s0 = e[0][0] + e[0][1] + e[1][0] + e[1][1];
        float s1 = e[0][2] + e[0][3] + e[1][2] + e[1][3];
        s0 += __shfl_xor_sync(0xffffffffu, s0, 1);
        s0 += __shfl_xor_sync(0xffffffffu, s0, 2);
        s1 += __shfl_xor_sync(0xffffffffu, s1, 1);
        s1 += __shfl_xor_sync(0xffffffffu, s1, 2);
        float inv0 = 1.f / s0, inv1 = 1.f / s1;
        uint32_t pa0 = pack_h2(e[0][0]*inv0, e[0][1]*inv0);
        uint32_t pa1 = pack_h2(e[0][2]*inv1, e[0][3]*inv1);
        uint32_t pa2 = pack_h2(e[1][0]*inv0, e[1][1]*inv0);
        uint32_t pa3 = pack_h2(e[1][2]*inv1, e[1][3]*inv1);
        float o[4][4];
#pragma unroll
        for (int j = 0; j < 4; j++) { o[j][0]=o[j][1]=o[j][2]=o[j][3]=0.f; }
        {
            uint32_t b0,b1r,b2,b3;
            ldsm4t(b0,b1r,b2,b3, sptr(vh + t_mrow*ASH + t_doff));
            mma_f16(o[0][0],o[0][1],o[0][2],o[0][3], pa0,pa1,pa2,pa3, b0,b1r);
            mma_f16(o[1][0],o[1][1],o[1][2],o[1][3], pa0,pa1,pa2,pa3, b2,b3);
            ldsm4t(b0,b1r,b2,b3, sptr(vh + t_mrow*ASH + 16 + t_doff));
            mma_f16(o[2][0],o[2][1],o[2][2],o[2][3], pa0,pa1,pa2,pa3, b0,b1r);
            mma_f16(o[3][0],o[3][1],o[3][2],o[3][3], pa0,pa1,pa2,pa3, b2,b3);
        }
#pragma unroll
        for (int j = 0; j < 4; j++) {
            int col = ho + j*8 + 2*t;
            *(__half2*)(xs + (b_loc*16 + g)*HSH + col)     = __floats2half2_rn(o[j][0], o[j][1]);
            *(__half2*)(xs + (b_loc*16 + g + 8)*HSH + col) = __floats2half2_rn(o[j][2], o[j][3]);
        }
        __syncwarp();
    }
    __syncthreads();

    /* proj: [64x256]@[256x256] + proj_b ; warp = 16 rows x 128 cols; 8 32-k chunks */
    {
        int mg = w >> 1, nh = w & 1;
        int a_row = mg*16 + (lane & 15);
        /* prefetch chunk 0 into aliased region (safe after barrier) */
        for (int i = tid; i < 256*4; i += 256) {
            int row = i >> 2, c8 = i & 3;
            cpa16(sptr(bsm + row*BC + c8*8), g_projh + row*256 + c8*8);
        }
        CPA_COMMIT();
        float acc[16][4];
#pragma unroll
        for (int nb = 0; nb < 16; nb++) {
            acc[nb][0]=0.f; acc[nb][1]=0.f; acc[nb][2]=0.f; acc[nb][3]=0.f;
        }
        for (int c = 0; c < 8; c++) {
            __half* bcur = bsm + (c & 1)*256*BC;
            CPA_WAIT0();
            __syncthreads();
            if (c < 7) {
                __half* bnxt = bsm + ((c + 1) & 1)*256*BC;
                const __half* src = g_projh + (c + 1)*32;
                for (int i = tid; i < 256*4; i += 256) {
                    int row = i >> 2, c8 = i & 3;
                    cpa16(sptr(bnxt + row*BC + c8*8), src + row*256 + c8*8);
                }
                CPA_COMMIT();
            }
#pragma unroll
            for (int kk = 0; kk < 2; kk++) {
                uint32_t A0[4];
                ldsm4(A0[0],A0[1],A0[2],A0[3],
                      sptr(xs + a_row*HSH + c*32 + kk*16 + a_koff));
#pragma unroll
                for (int np = 0; np < 8; np++) {
                    int cb = nh*128 + np*16 + b_nrow;
                    uint32_t b0,b1r,b2,b3;
                    ldsm4(b0,b1r,b2,b3, sptr(bcur + cb*BC + kk*16 + b_koff));
                    mma_f16(acc[2*np][0],acc[2*np][1],acc[2*np][2],acc[2*np][3],
                            A0[0],A0[1],A0[2],A0[3], b0,b1r);
                    mma_f16(acc[2*np+1][0],acc[2*np+1][1],acc[2*np+1][2],acc[2*np+1][3],
                            A0[0],A0[1],A0[2],A0[3], b2,b3);
                }
            }
        }
#pragma unroll
        for (int nb = 0; nb < 16; nb++) {
            int col = nh*128 + nb*8 + 2*t;
            int rowa = mg*16 + g;
            float bb0 = __ldg(&projb[col]), bb1 = __ldg(&projb[col+1]);
            long gr = (long)blockIdx.x*64 + rowa;
            *(float2*)(&out[gr*DIM + col])     = make_float2(acc[nb][0]+bb0, acc[nb][1]+bb1);
            *(float2*)(&out[(gr+8)*DIM + col]) = make_float2(acc[nb][2]+bb0, acc[nb][3]+bb1);
        }
    }
}

/* ---------------- launcher ---------------- */
extern "C" void kernel_launch(void* const* d_in, const int* in_sizes, int n_in,
                              void* d_out, int out_size) {
    (void)in_sizes; (void)n_in; (void)out_size;
    const float* x     = (const float*)d_in[0];
    const float* pr    = (const float*)d_in[1];
    const float* qkvw  = (const float*)d_in[2];
    const float* projw = (const float*)d_in[3];
    const float* projb = (const float*)d_in[4];
    const float* qw1 = (const float*)d_in[5];
    const float* qb1 = (const float*)d_in[6];
    const float* qg  = (const float*)d_in[7];
    const float* qbe = (const float*)d_in[8];
    const float* qw2 = (const float*)d_in[9];
    const float* qb2 = (const float*)d_in[10];
    const float* kw1 = (const float*)d_in[11];
    const float* kb1 = (const float*)d_in[12];
    const float* kg  = (const float*)d_in[13];
    const float* kbe = (const float*)d_in[14];
    const float* kw2 = (const float*)d_in[15];
    const float* kb2 = (const float*)d_in[16];
    const float* vw1 = (const float*)d_in[17];
    const float* vb1 = (const float*)d_in[18];
    const float* vg  = (const float*)d_in[19];
    const float* vbe = (const float*)d_in[20];
    const float* vw2 = (const float*)d_in[21];
    const float* vb2 = (const float*)d_in[22];

    const int smem_mlpqkv = (BSM_OFF + 2*128*B2SH) * 2;                 /* 200704 B */
    const int region = (2*16*QKS + 16*ASH) * 8 * 2;                     /* 47104 B  */
    const int projbuf = 2*256*BC*2;                                     /* 40960 B  */
    const int smem_ap = AP_REGION*2 + (region > projbuf ? region : projbuf); /* 80896 */
    cudaFuncSetAttribute(k_mlpqkv,   cudaFuncAttributeMaxDynamicSharedMemorySize, smem_mlpqkv);
    cudaFuncSetAttribute(k_attnproj, cudaFuncAttributeMaxDynamicSharedMemorySize, smem_ap);

    k_stats_part<<<256, 256>>>(pr);
    k_stats_red<<<10, 256>>>();
    k_prep<<<224, 512>>>(qkvw, qw2, kw2, vw2, projw);
    k_fold<<<96, 256>>>(qw1, qb1, qg, qbe, kw1, kb1, kg, kbe, vw1, vb1, vg, vbe);
    k_mlpqkv<<<1024, 256, smem_mlpqkv>>>(pr, qb2, kb2, vb2, x);
    k_attnproj<<<NROWS/64, 256, smem_ap>>>(projb, (float*)d_out);
}